// round 5
// baseline (speedup 1.0000x reference)
#include <cuda_runtime.h>
#include <cuda_bf16.h>

// Problem constants
#define SEQ   4096
#define EMB   128
#define HID   128
#define G4    512          // 4*HID gate rows
#define NT    16

// Scratch (device globals; no allocation allowed)
__device__ int   g_tok[SEQ];
__device__ float g_pre[(SEQ + 1) * G4];   // +1 row so prefetch never branches
__device__ float g_hs[SEQ * HID];

typedef unsigned long long ull;

// ---------------------------------------------------------------------------
// fast math helpers
// ---------------------------------------------------------------------------
__device__ __forceinline__ float f_ex2(float x) {
    float y; asm("ex2.approx.f32 %0, %1;" : "=f"(y) : "f"(x)); return y;
}
__device__ __forceinline__ float f_rcp(float x) {
    float y; asm("rcp.approx.f32 %0, %1;" : "=f"(y) : "f"(x)); return y;
}
__device__ __forceinline__ float f_sigmoid(float x) {
    return f_rcp(1.0f + f_ex2(-1.4426950408889634f * x));
}
__device__ __forceinline__ float f_tanh(float x) {
    return 2.0f * f_sigmoid(2.0f * x) - 1.0f;
}

// packed f32x2 FMA (sm_100+)
__device__ __forceinline__ ull ffma2(ull a, ull b, ull c) {
    ull d; asm("fma.rn.f32x2 %0, %1, %2, %3;" : "=l"(d) : "l"(a), "l"(b), "l"(c));
    return d;
}
__device__ __forceinline__ ull packf2(float lo, float hi) {
    ull r; asm("mov.b64 %0, {%1, %2};" : "=l"(r) : "f"(lo), "f"(hi)); return r;
}
__device__ __forceinline__ void unpackf2(float& lo, float& hi, ull v) {
    asm("mov.b64 {%0, %1}, %2;" : "=f"(lo), "=f"(hi) : "l"(v));
}
// one LDS.128 delivering two ready-to-use f32x2 operands
__device__ __forceinline__ void lds_v2b64(ull& a, ull& b, unsigned saddr) {
    asm volatile("ld.shared.v2.b64 {%0, %1}, [%2];" : "=l"(a), "=l"(b) : "r"(saddr));
}

// ---------------------------------------------------------------------------
// Kernel 0: normalize tokens to int32 (int64 delivered as 2x int32, or int32).
// ---------------------------------------------------------------------------
__global__ void tokenize_kernel(const int* __restrict__ xi) {
    __shared__ int is64;
    if (threadIdx.x == 0) {
        int nz = 0;
        #pragma unroll
        for (int i = 0; i < 64; ++i) nz += (xi[2 * i + 1] != 0);
        is64 = (nz == 0);
    }
    __syncthreads();
    int t = blockIdx.x * blockDim.x + threadIdx.x;
    if (t < SEQ) {
        if (is64) g_tok[t] = xi[2 * t];
        else      g_tok[t] = xi[t];
    }
}

// ---------------------------------------------------------------------------
// Kernel 1: pre[t][r] = b_ih[r] + b_hh[r] + sum_k emb[tok[t]][k] * w_ih[r][k]
// ---------------------------------------------------------------------------
__global__ void precompute_kernel(const float* __restrict__ emb,
                                  const float* __restrict__ w_ih,
                                  const float* __restrict__ b_ih,
                                  const float* __restrict__ b_hh,
                                  float* __restrict__ pre) {
    __shared__ float xe[16][128];
    const int t0 = blockIdx.x * 16;

    for (int i = threadIdx.x; i < 16 * 128; i += 256) {
        int ts = i >> 7, k = i & 127;
        long long tok = g_tok[t0 + ts];
        xe[ts][k] = emb[tok * (long long)EMB + k];
    }
    __syncthreads();

    #pragma unroll
    for (int rr = 0; rr < 2; ++rr) {
        const int r = threadIdx.x + rr * 256;
        const float bias = b_ih[r] + b_hh[r];
        float acc[16];
        #pragma unroll
        for (int ts = 0; ts < 16; ++ts) acc[ts] = bias;

        const float4* wrow = reinterpret_cast<const float4*>(w_ih + r * EMB);
        #pragma unroll 8
        for (int k4 = 0; k4 < EMB / 4; ++k4) {
            float4 w = wrow[k4];
            #pragma unroll
            for (int ts = 0; ts < 16; ++ts) {
                float4 h = reinterpret_cast<const float4*>(xe[ts])[k4];
                acc[ts] += w.x * h.x + w.y * h.y + w.z * h.z + w.w * h.w;
            }
        }
        #pragma unroll
        for (int ts = 0; ts < 16; ++ts)
            pre[(t0 + ts) * G4 + r] = acc[ts];
    }
}

// ---------------------------------------------------------------------------
// Kernel 2: recurrence. 1 block x 512 threads.
//   Thread t owns gate row  row = (t&3)*128 + (t>>2): the 4 gates of hidden
//   unit j = t>>2 sit in 4 adjacent lanes of one warp -> gate combine via
//   3 parallel shfl.idx, no smem round-trip, ONE barrier per step.
//   h double-buffered in smem (parity) so the single barrier is race-free.
//   Weights: row[0:96] in 48 packed f32x2 register pairs, row[96:128] in smem.
// ---------------------------------------------------------------------------
#define NREG   96
#define NSH    (HID - NREG)       // 32
#define WS_STRIDE 36              // 32 + 4 pad; conflict-free float4

__global__ void __launch_bounds__(512, 1)
lstm_kernel(const float* __restrict__ w_hh,
            const float* __restrict__ pre,
            float* __restrict__ hs) {
    extern __shared__ float smem[];
    float* ws  = smem;                          // 512 * 36 floats
    float* h_b = ws + G4 * WS_STRIDE;           // 2 x 128 floats (double buffer)

    const int t   = threadIdx.x;
    const int g   = t & 3;                      // gate: 0=i 1=f 2=g 3=o
    const int j   = t >> 2;                     // hidden unit
    const int row = g * 128 + j;

    // --- pack register weights: w_hh[row][0:96] -> 48 b64 pairs ---
    ull wreg[NREG / 2];
    {
        const float4* wrow = reinterpret_cast<const float4*>(w_hh + row * HID);
        #pragma unroll
        for (int i = 0; i < NREG / 4; ++i) {
            float4 w = wrow[i];
            wreg[2 * i]     = packf2(w.x, w.y);
            wreg[2 * i + 1] = packf2(w.z, w.w);
        }
    }
    // --- smem tail for row(t): ws[t][k] = w_hh[row][96+k] ---
    {
        const float4* wtail = reinterpret_cast<const float4*>(w_hh + row * HID + NREG);
        float4* wsrow4 = reinterpret_cast<float4*>(ws + t * WS_STRIDE);
        #pragma unroll
        for (int i = 0; i < NSH / 4; ++i) wsrow4[i] = wtail[i];
    }
    // --- init h buffer 0 ---
    if (t < HID) h_b[t] = 0.0f;
    float c = 0.0f;

    const unsigned h_base   = (unsigned)__cvta_generic_to_shared(h_b);
    const unsigned ws_saddr = (unsigned)__cvta_generic_to_shared(ws + t * WS_STRIDE);
    const bool is_tanh_gate = (g == 2);
    const int lane_base = (t & 31) & ~3;        // first lane of my 4-lane group

    float pre_cur = pre[row];
    __syncthreads();

    unsigned h_rd = h_base;                     // read buffer (parity 0)
    unsigned h_wr = h_base + 512u;              // write buffer

    for (int s = 0; s < SEQ; ++s) {
        ull acc0 = packf2(pre_cur, 0.0f);
        ull acc1 = 0;
        pre_cur = pre[(s + 1) * G4 + row];      // prefetch (row SEQ exists, unused)

        #pragma unroll
        for (int i = 0; i < NREG / 4; ++i) {            // register weight part
            ull hp0, hp1;
            lds_v2b64(hp0, hp1, h_rd + 16u * i);
            acc0 = ffma2(wreg[2 * i],     hp0, acc0);
            acc1 = ffma2(wreg[2 * i + 1], hp1, acc1);
        }
        #pragma unroll
        for (int i = 0; i < NSH / 4; ++i) {             // smem weight tail
            ull hp0, hp1, wp0, wp1;
            lds_v2b64(hp0, hp1, h_rd + 16u * (NREG / 4 + i));
            lds_v2b64(wp0, wp1, ws_saddr + 16u * i);
            acc0 = ffma2(wp0, hp0, acc0);
            acc1 = ffma2(wp1, hp1, acc1);
        }

        float s0, s1, s2, s3;
        unpackf2(s0, s1, acc0);
        unpackf2(s2, s3, acc1);
        float z = (s0 + s1) + (s2 + s3);

        // per-lane activation for my gate
        float a = is_tanh_gate ? f_tanh(z) : f_sigmoid(z);

        // gather f,g,o into the i-lane (3 independent shfls, depth 1)
        float af = __shfl_sync(0xffffffffu, a, lane_base + 1);
        float ag = __shfl_sync(0xffffffffu, a, lane_base + 2);
        float ao = __shfl_sync(0xffffffffu, a, lane_base + 3);

        if (g == 0) {
            c = af * c + a * ag;                // a == i-gate activation
            float hv = ao * f_tanh(c);
            asm volatile("st.shared.f32 [%0], %1;"
                         :: "r"(h_wr + 4u * j), "f"(hv));
            hs[s * HID + j] = hv;
        }

        // swap h buffers; one barrier per step
        unsigned tmp = h_rd; h_rd = h_wr; h_wr = tmp;
        __syncthreads();
    }
}

// ---------------------------------------------------------------------------
// Kernel 3: out[t][n] = b_fc[n] + sum_k hs[t][k] * w_fc[n][k]
// ---------------------------------------------------------------------------
__global__ void fc_kernel(const float* __restrict__ hs,
                          const float* __restrict__ w_fc,
                          const float* __restrict__ b_fc,
                          float* __restrict__ out) {
    __shared__ float sh[16][132];
    __shared__ float sw[16][132];
    const int t0 = blockIdx.x * 16;

    for (int i = threadIdx.x; i < 16 * 128; i += 256) {
        int r = i >> 7, k = i & 127;
        sh[r][k] = hs[(t0 + r) * HID + k];
        sw[r][k] = w_fc[r * HID + k];
    }
    __syncthreads();

    const int ts = threadIdx.x >> 4;
    const int n  = threadIdx.x & 15;
    float acc = b_fc[n];
    #pragma unroll 8
    for (int k = 0; k < 128; ++k)
        acc += sh[ts][k] * sw[n][k];
    out[(t0 + ts) * NT + n] = acc;
}

// ---------------------------------------------------------------------------
extern "C" void kernel_launch(void* const* d_in, const int* in_sizes, int n_in,
                              void* d_out, int out_size) {
    const int*   x    = (const int*)d_in[0];
    const float* emb  = (const float*)d_in[1];
    const float* w_ih = (const float*)d_in[2];
    const float* w_hh = (const float*)d_in[3];
    const float* b_ih = (const float*)d_in[4];
    const float* b_hh = (const float*)d_in[5];
    const float* w_fc = (const float*)d_in[6];
    const float* b_fc = (const float*)d_in[7];
    float* out = (float*)d_out;

    float* pre; cudaGetSymbolAddress((void**)&pre, g_pre);
    float* hs;  cudaGetSymbolAddress((void**)&hs,  g_hs);

    const int lstm_smem = (G4 * WS_STRIDE + 2 * HID) * (int)sizeof(float);
    cudaFuncSetAttribute(lstm_kernel,
                         cudaFuncAttributeMaxDynamicSharedMemorySize, lstm_smem);

    tokenize_kernel<<<SEQ / 256, 256>>>(x);
    precompute_kernel<<<SEQ / 16, 256>>>(emb, w_ih, b_ih, b_hh, pre);
    lstm_kernel<<<1, 512, lstm_smem>>>(w_hh, pre, hs);
    fc_kernel<<<SEQ / 16, 256>>>(hs, w_fc, b_fc, out);
}